// round 14
// baseline (speedup 1.0000x reference)
#include <cuda_runtime.h>

// SIR RK4: B=65536 systems, params[b]=(beta,gamma,S0,I0), out[b][t][3], 199 steps.
//
// R12: SMEM-staged coalesced stores. R8/R11 showed diverged STG (32 wavefronts per
// warp-store, ~66k L1 cycles/SM) is the exposed-latency wall once compute shrank.
// Each block (64 threads = 64 consecutive systems, rows contiguous in GMEM) stages
// 40 timesteps (120 floats/row, pitch 121 -> conflict-free) in SMEM, then flushes
// linearly: consecutive lanes write consecutive floats of a row -> full-line
// coalesced STG.32. GMEM store wavefronts drop 32x. SUBSTEPS=2 kept (rel_err
// 1.09e-6 measured, ~900x under the 1e-3 gate).

#define NUM_T    200
#define SUBSTEPS 2
#define WIN_T    40                 // timesteps staged per window (5 windows x 40 = 200)
#define ROW_F    (WIN_T * 3)        // 120 floats per row per window
#define PITCH    (ROW_F + 1)        // 121 floats: 121 mod 32 = 25 (odd) -> conflict-free
#define BLOCK    64

struct Coef {
    float h2b, hb, c6b, h2g, hg, c6g;
};

__device__ __forceinline__ void rk4_step(float& S, float& I, const Coef& c)
{
#pragma unroll
    for (int s = 0; s < SUBSTEPS; ++s) {
        // stage 1 at (S, I)
        float u1  = S * I;
        float in1 = fmaf(-c.h2g, I, I);
        float S2  = fmaf(-c.h2b, u1, S);
        float I2  = fmaf( c.h2b, u1, in1);
        // stage 2 at (S2, I2)
        float u2  = S2 * I2;
        float in2 = fmaf(-c.h2g, I2, I);
        float S3  = fmaf(-c.h2b, u2, S);
        float I3  = fmaf( c.h2b, u2, in2);
        // stage 3 at (S3, I3), full step
        float u3  = S3 * I3;
        float in3 = fmaf(-c.hg, I3, I);
        float S4  = fmaf(-c.hb, u3, S);
        float I4  = fmaf( c.hb, u3, in3);
        // stage 4
        float u4  = S4 * I4;
        // weighted sums (off the critical path)
        float accU = fmaf(2.0f, u2, u1);
        accU       = fmaf(2.0f, u3, accU);
        accU       = accU + u4;
        float accI = fmaf(2.0f, I2, I);
        accI       = fmaf(2.0f, I3, accI);
        accI       = accI + I4;
        // combine
        S        = fmaf(-c.c6b, accU, S);
        float tI = fmaf( c.c6b, accU, I);
        I        = fmaf(-c.c6g, accI, tI);
    }
}

__global__ __launch_bounds__(BLOCK)
void sir_rk4_kernel(const float* __restrict__ params,
                    float* __restrict__ out)
{
    __shared__ float stage[BLOCK * PITCH];      // 64 * 121 * 4 = 30,976 B

    const int tid = threadIdx.x;
    const int b   = blockIdx.x * BLOCK + tid;   // grid*block == B exactly

    const float4 p = reinterpret_cast<const float4*>(params)[b];
    float S = p.z;
    float I = p.w;

    const float DT = 100.0f / 199.0f;
    const float H  = DT / (float)SUBSTEPS;
    Coef c;
    c.h2b = 0.5f * H * p.x;
    c.hb  = H * p.x;
    c.c6b = (H / 6.0f) * p.x;
    c.h2g = 0.5f * H * p.y;
    c.hg  = H * p.y;
    c.c6g = (H / 6.0f) * p.y;

    // GMEM base of this block's 64 contiguous rows
    float* blk_out = out + (size_t)blockIdx.x * BLOCK * (NUM_T * 3);
    float* myrow   = &stage[tid * PITCH];

#pragma unroll 1
    for (int w = 0; w < NUM_T / WIN_T; ++w) {
        // ---- compute phase: fill my staged row ----
        int cc = 0;
        if (w == 0) {                            // t = 0 snapshot
            myrow[0] = S;
            myrow[1] = I;
            myrow[2] = 1.0f - S - I;
            cc = 3;
        }
        const int nsteps = (w == 0) ? (WIN_T - 1) : WIN_T;
#pragma unroll 1
        for (int s = 0; s < nsteps; ++s) {
            rk4_step(S, I, c);
            myrow[cc]     = S;
            myrow[cc + 1] = I;
            myrow[cc + 2] = 1.0f - S - I;
            cc += 3;
        }
        __syncthreads();

        // ---- flush phase: coalesced linear copy SMEM -> GMEM ----
        // element i -> row r = i/ROW_F, col = i%ROW_F
        // consecutive lanes -> consecutive cols of one row -> coalesced STG.32
        float* dst = blk_out + w * ROW_F;
#pragma unroll 1
        for (int i = tid; i < BLOCK * ROW_F; i += BLOCK) {
            int r  = i / ROW_F;
            int col = i - r * ROW_F;
            dst[r * (NUM_T * 3) + col] = stage[r * PITCH + col];
        }
        __syncthreads();
    }
}

extern "C" void kernel_launch(void* const* d_in, const int* in_sizes, int n_in,
                              void* d_out, int out_size)
{
    const float* params = (const float*)d_in[0];
    float* out = (float*)d_out;
    const int B = in_sizes[0] / 4;          // 65536

    const int grid = B / BLOCK;             // 1024 blocks, exact cover
    sir_rk4_kernel<<<grid, BLOCK>>>(params, out);
}

// round 15
// speedup vs baseline: 1.6940x; 1.6940x over previous
#include <cuda_runtime.h>

// SIR RK4: B=65536 systems, params[b]=(beta,gamma,S0,I0), out[b][t][3], 199 steps.
//
// R15: R12's SMEM staging with the two measured fixes:
//  (a) flush rewritten: no div/mod, float4 LDS/STG, incremental addressing.
//      PITCH4=31 float4 (124 floats): compute STS.128 and flush LDS.128 both
//      bank-conflict-free (lane-phase stride 28 / 4 mod 32 hit distinct banks).
//  (b) SUBSTEPS=1: truncation ladder measured across S8/S4/S2 (x16 per halving,
//      trunc(S2)~5e-7) -> trunc(S1)~8e-6, ~100x under the 1e-3 gate.

#define NUM_T    200
#define SUBSTEPS 1
#define WIN_T    40                  // 5 windows x 40 t-steps
#define ROW_F4   30                  // 40*3 floats = 30 float4 per row-window
#define PITCH4   31                  // float4 pitch; conflict-free both phases
#define BLOCK    64

struct Coef {
    float h2b, hb, c6b, h2g, hg, c6g;
};

__device__ __forceinline__ void rk4_step(float& S, float& I, const Coef& c)
{
#pragma unroll
    for (int s = 0; s < SUBSTEPS; ++s) {
        // stage 1 at (S, I)
        float u1  = S * I;
        float in1 = fmaf(-c.h2g, I, I);
        float S2  = fmaf(-c.h2b, u1, S);
        float I2  = fmaf( c.h2b, u1, in1);
        // stage 2 at (S2, I2)
        float u2  = S2 * I2;
        float in2 = fmaf(-c.h2g, I2, I);
        float S3  = fmaf(-c.h2b, u2, S);
        float I3  = fmaf( c.h2b, u2, in2);
        // stage 3 at (S3, I3), full step
        float u3  = S3 * I3;
        float in3 = fmaf(-c.hg, I3, I);
        float S4  = fmaf(-c.hb, u3, S);
        float I4  = fmaf( c.hb, u3, in3);
        // stage 4
        float u4  = S4 * I4;
        // weighted sums
        float accU = fmaf(2.0f, u2, u1);
        accU       = fmaf(2.0f, u3, accU);
        accU       = accU + u4;
        float accI = fmaf(2.0f, I2, I);
        accI       = fmaf(2.0f, I3, accI);
        accI       = accI + I4;
        // combine
        S        = fmaf(-c.c6b, accU, S);
        float tI = fmaf( c.c6b, accU, I);
        I        = fmaf(-c.c6g, accI, tI);
    }
}

__global__ __launch_bounds__(BLOCK)
void sir_rk4_kernel(const float* __restrict__ params,
                    float* __restrict__ out)
{
    __shared__ float4 stage[BLOCK * PITCH4];    // 64*31*16 = 31,744 B -> 7 blocks/SM

    const int tid = threadIdx.x;
    const int b   = blockIdx.x * BLOCK + tid;   // grid*block == B exactly

    const float4 p = reinterpret_cast<const float4*>(params)[b];
    float S = p.z;
    float I = p.w;

    const float DT = 100.0f / 199.0f;
    const float H  = DT / (float)SUBSTEPS;
    Coef c;
    c.h2b = 0.5f * H * p.x;
    c.hb  = H * p.x;
    c.c6b = (H / 6.0f) * p.x;
    c.h2g = 0.5f * H * p.y;
    c.hg  = H * p.y;
    c.c6g = (H / 6.0f) * p.y;

    // GMEM, in float4 units: row stride = 600 floats = 150 float4 (16B-aligned)
    float4* blk4  = reinterpret_cast<float4*>(out + (size_t)blockIdx.x * BLOCK * (NUM_T * 3));
    float4* myrow = stage + tid * PITCH4;

    const int lane = tid & 31;
    const int wid  = tid >> 5;

#pragma unroll 1
    for (int w = 0; w < NUM_T / WIN_T; ++w) {
        // ---- compute phase: 10 groups of 4 t-steps -> 3 STS.128 each ----
        int g0 = 0;
        if (w == 0) {
            float4 b0, b1, b2;
            b0.x = S; b0.y = I; b0.z = 1.0f - S - I;           // t = 0 snapshot
            rk4_step(S, I, c);
            b0.w = S; b1.x = I; b1.y = 1.0f - S - I;
            rk4_step(S, I, c);
            b1.z = S; b1.w = I; b2.x = 1.0f - S - I;
            rk4_step(S, I, c);
            b2.y = S; b2.z = I; b2.w = 1.0f - S - I;
            myrow[0] = b0; myrow[1] = b1; myrow[2] = b2;
            g0 = 1;
        }
#pragma unroll 1
        for (int g = g0; g < WIN_T / 4; ++g) {
            float4 b0, b1, b2;
            rk4_step(S, I, c);
            b0.x = S; b0.y = I; b0.z = 1.0f - S - I;
            rk4_step(S, I, c);
            b0.w = S; b1.x = I; b1.y = 1.0f - S - I;
            rk4_step(S, I, c);
            b1.z = S; b1.w = I; b2.x = 1.0f - S - I;
            rk4_step(S, I, c);
            b2.y = S; b2.z = I; b2.w = 1.0f - S - I;
            float4* o = myrow + g * 3;
            o[0] = b0; o[1] = b1; o[2] = b2;
        }
        __syncthreads();

        // ---- flush phase: per warp, 32 rows; lane l copies float4 l of each row.
        // No division; addresses advance by constants. LDS.128/STG.128, conflict-free.
        if (lane < ROW_F4) {
            const float4* src = stage + (wid * 32) * PITCH4 + lane;
            float4*       dst = blk4 + (wid * 32) * 150 + w * ROW_F4 + lane;
#pragma unroll 8
            for (int rr = 0; rr < 32; ++rr) {
                *dst = *src;
                src += PITCH4;
                dst += 150;
            }
        }
        __syncthreads();
    }
}

extern "C" void kernel_launch(void* const* d_in, const int* in_sizes, int n_in,
                              void* d_out, int out_size)
{
    const float* params = (const float*)d_in[0];
    float* out = (float*)d_out;
    const int B = in_sizes[0] / 4;          // 65536

    const int grid = B / BLOCK;             // 1024 blocks, exact cover
    sir_rk4_kernel<<<grid, BLOCK>>>(params, out);
}

// round 16
// speedup vs baseline: 1.7052x; 1.0067x over previous
#include <cuda_runtime.h>

// SIR RK4: B=65536 systems, params[b]=(beta,gamma,S0,I0), out[b][t][3], 199 steps.
//
// R15: R12's SMEM staging with the two measured fixes:
//  (a) flush rewritten: no div/mod, float4 LDS/STG, incremental addressing.
//      PITCH4=31 float4 (124 floats): compute STS.128 and flush LDS.128 both
//      bank-conflict-free (lane-phase stride 28 / 4 mod 32 hit distinct banks).
//  (b) SUBSTEPS=1: truncation ladder measured across S8/S4/S2 (x16 per halving,
//      trunc(S2)~5e-7) -> trunc(S1)~8e-6, ~100x under the 1e-3 gate.

#define NUM_T    200
#define SUBSTEPS 1
#define WIN_T    40                  // 5 windows x 40 t-steps
#define ROW_F4   30                  // 40*3 floats = 30 float4 per row-window
#define PITCH4   31                  // float4 pitch; conflict-free both phases
#define BLOCK    64

struct Coef {
    float h2b, hb, c6b, h2g, hg, c6g;
};

__device__ __forceinline__ void rk4_step(float& S, float& I, const Coef& c)
{
#pragma unroll
    for (int s = 0; s < SUBSTEPS; ++s) {
        // stage 1 at (S, I)
        float u1  = S * I;
        float in1 = fmaf(-c.h2g, I, I);
        float S2  = fmaf(-c.h2b, u1, S);
        float I2  = fmaf( c.h2b, u1, in1);
        // stage 2 at (S2, I2)
        float u2  = S2 * I2;
        float in2 = fmaf(-c.h2g, I2, I);
        float S3  = fmaf(-c.h2b, u2, S);
        float I3  = fmaf( c.h2b, u2, in2);
        // stage 3 at (S3, I3), full step
        float u3  = S3 * I3;
        float in3 = fmaf(-c.hg, I3, I);
        float S4  = fmaf(-c.hb, u3, S);
        float I4  = fmaf( c.hb, u3, in3);
        // stage 4
        float u4  = S4 * I4;
        // weighted sums
        float accU = fmaf(2.0f, u2, u1);
        accU       = fmaf(2.0f, u3, accU);
        accU       = accU + u4;
        float accI = fmaf(2.0f, I2, I);
        accI       = fmaf(2.0f, I3, accI);
        accI       = accI + I4;
        // combine
        S        = fmaf(-c.c6b, accU, S);
        float tI = fmaf( c.c6b, accU, I);
        I        = fmaf(-c.c6g, accI, tI);
    }
}

__global__ __launch_bounds__(BLOCK)
void sir_rk4_kernel(const float* __restrict__ params,
                    float* __restrict__ out)
{
    __shared__ float4 stage[BLOCK * PITCH4];    // 64*31*16 = 31,744 B -> 7 blocks/SM

    const int tid = threadIdx.x;
    const int b   = blockIdx.x * BLOCK + tid;   // grid*block == B exactly

    const float4 p = reinterpret_cast<const float4*>(params)[b];
    float S = p.z;
    float I = p.w;

    const float DT = 100.0f / 199.0f;
    const float H  = DT / (float)SUBSTEPS;
    Coef c;
    c.h2b = 0.5f * H * p.x;
    c.hb  = H * p.x;
    c.c6b = (H / 6.0f) * p.x;
    c.h2g = 0.5f * H * p.y;
    c.hg  = H * p.y;
    c.c6g = (H / 6.0f) * p.y;

    // GMEM, in float4 units: row stride = 600 floats = 150 float4 (16B-aligned)
    float4* blk4  = reinterpret_cast<float4*>(out + (size_t)blockIdx.x * BLOCK * (NUM_T * 3));
    float4* myrow = stage + tid * PITCH4;

    const int lane = tid & 31;
    const int wid  = tid >> 5;

#pragma unroll 1
    for (int w = 0; w < NUM_T / WIN_T; ++w) {
        // ---- compute phase: 10 groups of 4 t-steps -> 3 STS.128 each ----
        int g0 = 0;
        if (w == 0) {
            float4 b0, b1, b2;
            b0.x = S; b0.y = I; b0.z = 1.0f - S - I;           // t = 0 snapshot
            rk4_step(S, I, c);
            b0.w = S; b1.x = I; b1.y = 1.0f - S - I;
            rk4_step(S, I, c);
            b1.z = S; b1.w = I; b2.x = 1.0f - S - I;
            rk4_step(S, I, c);
            b2.y = S; b2.z = I; b2.w = 1.0f - S - I;
            myrow[0] = b0; myrow[1] = b1; myrow[2] = b2;
            g0 = 1;
        }
#pragma unroll 1
        for (int g = g0; g < WIN_T / 4; ++g) {
            float4 b0, b1, b2;
            rk4_step(S, I, c);
            b0.x = S; b0.y = I; b0.z = 1.0f - S - I;
            rk4_step(S, I, c);
            b0.w = S; b1.x = I; b1.y = 1.0f - S - I;
            rk4_step(S, I, c);
            b1.z = S; b1.w = I; b2.x = 1.0f - S - I;
            rk4_step(S, I, c);
            b2.y = S; b2.z = I; b2.w = 1.0f - S - I;
            float4* o = myrow + g * 3;
            o[0] = b0; o[1] = b1; o[2] = b2;
        }
        __syncthreads();

        // ---- flush phase: per warp, 32 rows; lane l copies float4 l of each row.
        // No division; addresses advance by constants. LDS.128/STG.128, conflict-free.
        if (lane < ROW_F4) {
            const float4* src = stage + (wid * 32) * PITCH4 + lane;
            float4*       dst = blk4 + (wid * 32) * 150 + w * ROW_F4 + lane;
#pragma unroll 8
            for (int rr = 0; rr < 32; ++rr) {
                *dst = *src;
                src += PITCH4;
                dst += 150;
            }
        }
        __syncthreads();
    }
}

extern "C" void kernel_launch(void* const* d_in, const int* in_sizes, int n_in,
                              void* d_out, int out_size)
{
    const float* params = (const float*)d_in[0];
    float* out = (float*)d_out;
    const int B = in_sizes[0] / 4;          // 65536

    const int grid = B / BLOCK;             // 1024 blocks, exact cover
    sir_rk4_kernel<<<grid, BLOCK>>>(params, out);
}